// round 2
// baseline (speedup 1.0000x reference)
#include <cuda_runtime.h>
#include <math.h>

#define NE   16
#define NU   8
#define NA   4
#define NSV  256
#define NPV  32
#define PSTR 33     // padded pair-row stride (floats) to avoid 32-way bank conflicts
#define NFB  4
#define NDET 16
#define NORB 128    // N_U * N_DET
#define NTH  256

struct SM {
    float s_a[NE * NSV];        // 4096
    float s_b[NE * NSV];        // 4096
    float p[NE * NE * PSTR];    // 8448
    float mu[NSV];
    float md[NSV];
    float pu[NE * NPV];
    float pd[NE * NPV];
    float base[NSV];
    float pw[NPV * NPV];
    float pbv[NPV];
    float r_s[NE * 3];
    float a_s[NA * 3];
    float env[NE];
    float sw[NE * NORB];        // 2048
    float ldv[2 * NDET];
    float sgv[2 * NDET];
};

// ---------------------------------------------------------------------------
// s-stream matmul: out[e][c] = tanh( bias[c] + sum_k s[e][k] W_s[k][c]
//                                    + mu@W_mu + md@W_md + pu[e]@W_pu + pd[e]@W_pd )
//                              (+ s[e][c] if RES)
// W layout: rows [0,KS) s, [KS,2KS) mu, [2KS,3KS) md, [3KS,3KS+KP) pu,
//           [3KS+KP, 3KS+2KP) pd; row stride NSV.
// mu/md contribution is row-independent -> computed once into base[] (phase 1).
// ---------------------------------------------------------------------------
template <int KS, int KP, bool RES>
__device__ __forceinline__ void fb_matmul(SM* sm,
                                          const float* __restrict__ W,
                                          const float* __restrict__ bias,
                                          const float* sin_, float* sout,
                                          int tid) {
    // Phase 1: base[c] (one column per thread, coalesced global reads)
    {
        float am = __ldg(bias + tid);
        float ad = 0.f;
        const float* Wm = W + KS * NSV + tid;
        const float* Wd = W + 2 * KS * NSV + tid;
#pragma unroll 4
        for (int k = 0; k < KS; ++k) {
            am = fmaf(sm->mu[k], __ldg(Wm + k * NSV), am);
            ad = fmaf(sm->md[k], __ldg(Wd + k * NSV), ad);
        }
        sm->base[tid] = am + ad;
    }
    __syncthreads();

    // Phase 2: 4 rows x 4 cols per thread
    const int r0 = (tid >> 6) << 2;   // warp-uniform -> SMEM broadcast loads
    const int c0 = (tid & 63) << 2;   // lane-contiguous -> coalesced float4 LDG
    float4 b4 = *reinterpret_cast<const float4*>(sm->base + c0);
    float acc[4][4];
#pragma unroll
    for (int ri = 0; ri < 4; ++ri) {
        acc[ri][0] = b4.x; acc[ri][1] = b4.y; acc[ri][2] = b4.z; acc[ri][3] = b4.w;
    }
    const float* s0 = sin_ + (r0 + 0) * NSV;
    const float* s1 = sin_ + (r0 + 1) * NSV;
    const float* s2 = sin_ + (r0 + 2) * NSV;
    const float* s3 = sin_ + (r0 + 3) * NSV;
    const float4* Wc = reinterpret_cast<const float4*>(W) + (c0 >> 2);
#pragma unroll 4
    for (int k = 0; k < KS; ++k) {
        float4 w = __ldg(Wc + k * (NSV / 4));
        float v0 = s0[k], v1 = s1[k], v2 = s2[k], v3 = s3[k];
        acc[0][0] = fmaf(v0, w.x, acc[0][0]); acc[0][1] = fmaf(v0, w.y, acc[0][1]);
        acc[0][2] = fmaf(v0, w.z, acc[0][2]); acc[0][3] = fmaf(v0, w.w, acc[0][3]);
        acc[1][0] = fmaf(v1, w.x, acc[1][0]); acc[1][1] = fmaf(v1, w.y, acc[1][1]);
        acc[1][2] = fmaf(v1, w.z, acc[1][2]); acc[1][3] = fmaf(v1, w.w, acc[1][3]);
        acc[2][0] = fmaf(v2, w.x, acc[2][0]); acc[2][1] = fmaf(v2, w.y, acc[2][1]);
        acc[2][2] = fmaf(v2, w.z, acc[2][2]); acc[2][3] = fmaf(v2, w.w, acc[2][3]);
        acc[3][0] = fmaf(v3, w.x, acc[3][0]); acc[3][1] = fmaf(v3, w.y, acc[3][1]);
        acc[3][2] = fmaf(v3, w.z, acc[3][2]); acc[3][3] = fmaf(v3, w.w, acc[3][3]);
    }
    {
        const float4* Wpu = reinterpret_cast<const float4*>(W + 3 * KS * NSV) + (c0 >> 2);
        const float* q0 = sm->pu + (r0 + 0) * NPV;
        const float* q1 = sm->pu + (r0 + 1) * NPV;
        const float* q2 = sm->pu + (r0 + 2) * NPV;
        const float* q3 = sm->pu + (r0 + 3) * NPV;
#pragma unroll
        for (int k = 0; k < KP; ++k) {
            float4 w = __ldg(Wpu + k * (NSV / 4));
            float v0 = q0[k], v1 = q1[k], v2 = q2[k], v3 = q3[k];
            acc[0][0] = fmaf(v0, w.x, acc[0][0]); acc[0][1] = fmaf(v0, w.y, acc[0][1]);
            acc[0][2] = fmaf(v0, w.z, acc[0][2]); acc[0][3] = fmaf(v0, w.w, acc[0][3]);
            acc[1][0] = fmaf(v1, w.x, acc[1][0]); acc[1][1] = fmaf(v1, w.y, acc[1][1]);
            acc[1][2] = fmaf(v1, w.z, acc[1][2]); acc[1][3] = fmaf(v1, w.w, acc[1][3]);
            acc[2][0] = fmaf(v2, w.x, acc[2][0]); acc[2][1] = fmaf(v2, w.y, acc[2][1]);
            acc[2][2] = fmaf(v2, w.z, acc[2][2]); acc[2][3] = fmaf(v2, w.w, acc[2][3]);
            acc[3][0] = fmaf(v3, w.x, acc[3][0]); acc[3][1] = fmaf(v3, w.y, acc[3][1]);
            acc[3][2] = fmaf(v3, w.z, acc[3][2]); acc[3][3] = fmaf(v3, w.w, acc[3][3]);
        }
    }
    {
        const float4* Wpd = reinterpret_cast<const float4*>(W + (3 * KS + KP) * NSV) + (c0 >> 2);
        const float* q0 = sm->pd + (r0 + 0) * NPV;
        const float* q1 = sm->pd + (r0 + 1) * NPV;
        const float* q2 = sm->pd + (r0 + 2) * NPV;
        const float* q3 = sm->pd + (r0 + 3) * NPV;
#pragma unroll
        for (int k = 0; k < KP; ++k) {
            float4 w = __ldg(Wpd + k * (NSV / 4));
            float v0 = q0[k], v1 = q1[k], v2 = q2[k], v3 = q3[k];
            acc[0][0] = fmaf(v0, w.x, acc[0][0]); acc[0][1] = fmaf(v0, w.y, acc[0][1]);
            acc[0][2] = fmaf(v0, w.z, acc[0][2]); acc[0][3] = fmaf(v0, w.w, acc[0][3]);
            acc[1][0] = fmaf(v1, w.x, acc[1][0]); acc[1][1] = fmaf(v1, w.y, acc[1][1]);
            acc[1][2] = fmaf(v1, w.z, acc[1][2]); acc[1][3] = fmaf(v1, w.w, acc[1][3]);
            acc[2][0] = fmaf(v2, w.x, acc[2][0]); acc[2][1] = fmaf(v2, w.y, acc[2][1]);
            acc[2][2] = fmaf(v2, w.z, acc[2][2]); acc[2][3] = fmaf(v2, w.w, acc[2][3]);
            acc[3][0] = fmaf(v3, w.x, acc[3][0]); acc[3][1] = fmaf(v3, w.y, acc[3][1]);
            acc[3][2] = fmaf(v3, w.z, acc[3][2]); acc[3][3] = fmaf(v3, w.w, acc[3][3]);
        }
    }
#pragma unroll
    for (int ri = 0; ri < 4; ++ri) {
        float4 o;
        o.x = tanhf(acc[ri][0]); o.y = tanhf(acc[ri][1]);
        o.z = tanhf(acc[ri][2]); o.w = tanhf(acc[ri][3]);
        if (RES) {
            float4 rr = *reinterpret_cast<const float4*>(sin_ + (r0 + ri) * NSV + c0);
            o.x += rr.x; o.y += rr.y; o.z += rr.z; o.w += rr.w;
        }
        *reinterpret_cast<float4*>(sout + (r0 + ri) * NSV + c0) = o;
    }
    __syncthreads();
}

// p-stream: one pair-row per thread, weights staged in SMEM.
template <int KIN, bool RES>
__device__ __forceinline__ void p_matmul(SM* sm, const float* __restrict__ W,
                                         const float* __restrict__ bias, int tid) {
    for (int i = tid; i < KIN * NPV; i += NTH) sm->pw[i] = __ldg(W + i);
    if (tid < NPV) sm->pbv[tid] = __ldg(bias + tid);
    __syncthreads();
    float* prow = sm->p + tid * PSTR;
    float pin[KIN];
#pragma unroll
    for (int k = 0; k < KIN; ++k) pin[k] = prow[k];
#pragma unroll 4
    for (int c = 0; c < NPV; ++c) {
        float acc = sm->pbv[c];
#pragma unroll
        for (int k = 0; k < KIN; ++k) acc = fmaf(pin[k], sm->pw[k * NPV + c], acc);
        float v = tanhf(acc);
        if (RES) v += pin[c];
        prow[c] = v;
    }
    __syncthreads();
}

__device__ __forceinline__ void means_s(SM* sm, const float* s, int ks, int tid) {
    if (tid < ks) {
        float a = 0.f, b = 0.f;
#pragma unroll
        for (int e = 0; e < NU; ++e) a += s[e * NSV + tid];
#pragma unroll
        for (int e = NU; e < NE; ++e) b += s[e * NSV + tid];
        sm->mu[tid] = a * 0.125f;
        sm->md[tid] = b * 0.125f;
    }
}

__device__ __forceinline__ void means_p(SM* sm, int kp, int tid) {
    for (int idx = tid; idx < NE * NPV; idx += NTH) {
        int j = idx >> 5, f = idx & 31;
        if (f < kp) {
            float a = 0.f, b = 0.f;
#pragma unroll
            for (int i = 0; i < NU; ++i) a += sm->p[(i * NE + j) * PSTR + f];
#pragma unroll
            for (int i = NU; i < NE; ++i) b += sm->p[(i * NE + j) * PSTR + f];
            sm->pu[j * NPV + f] = a * 0.125f;
            sm->pd[j * NPV + f] = b * 0.125f;
        }
    }
}

__global__ void __launch_bounds__(NTH, 2) ansatz_kernel(
    const float* __restrict__ r, const float* __restrict__ a,
    const float* __restrict__ sW0, const float* __restrict__ sb0,
    const float* __restrict__ sW, const float* __restrict__ sb,
    const float* __restrict__ pW0, const float* __restrict__ pb0,
    const float* __restrict__ pW, const float* __restrict__ pb,
    const float* __restrict__ vW, const float* __restrict__ vb,
    const float* __restrict__ wuW, const float* __restrict__ wub,
    const float* __restrict__ wdW, const float* __restrict__ wdb,
    const float* __restrict__ wfW, float* __restrict__ out) {
    extern __shared__ float smem_raw[];
    SM* sm = reinterpret_cast<SM*>(smem_raw);
    const int tid = threadIdx.x;
    const int b = blockIdx.x;

    if (tid < NE * 3) sm->r_s[tid] = r[b * NE * 3 + tid];
    if (tid >= 64 && tid < 64 + NA * 3) sm->a_s[tid - 64] = a[tid - 64];
    __syncthreads();

    // ---- embedding ----
    if (tid < NE) {
        int e = tid;
        float rx = sm->r_s[e * 3], ry = sm->r_s[e * 3 + 1], rz = sm->r_s[e * 3 + 2];
        float envv = 0.f;
#pragma unroll
        for (int at = 0; at < NA; ++at) {
            float dx = rx - sm->a_s[at * 3];
            float dy = ry - sm->a_s[at * 3 + 1];
            float dz = rz - sm->a_s[at * 3 + 2];
            float l = sqrtf(dx * dx + dy * dy + dz * dz);
            sm->s_a[e * NSV + at * 4 + 0] = dx;
            sm->s_a[e * NSV + at * 4 + 1] = dy;
            sm->s_a[e * NSV + at * 4 + 2] = dz;
            sm->s_a[e * NSV + at * 4 + 3] = l;
            envv += expf(-l);
        }
        sm->env[e] = envv;
    }
    {
        int i = tid >> 4, j = tid & 15;
        float dx = sm->r_s[j * 3 + 0] - sm->r_s[i * 3 + 0];
        float dy = sm->r_s[j * 3 + 1] - sm->r_s[i * 3 + 1];
        float dz = sm->r_s[j * 3 + 2] - sm->r_s[i * 3 + 2];
        float l = (i == j) ? sqrtf(3.0f) : sqrtf(dx * dx + dy * dy + dz * dz);
        float* prow = sm->p + tid * PSTR;
        prow[0] = dx; prow[1] = dy; prow[2] = dz; prow[3] = l;
    }
    __syncthreads();

    // ---- layer 0 ----
    means_s(sm, sm->s_a, 16, tid);
    means_p(sm, 4, tid);
    __syncthreads();
    fb_matmul<16, 4, false>(sm, sW0, sb0, sm->s_a, sm->s_b, tid);
    p_matmul<4, false>(sm, pW0, pb0, tid);

    // ---- residual layers ----
    float* cur = sm->s_b;
    float* oth = sm->s_a;
    for (int l = 0; l < NFB; ++l) {
        means_s(sm, cur, NSV, tid);
        means_p(sm, NPV, tid);
        __syncthreads();
        fb_matmul<256, 32, true>(sm, sW + l * (832 * NSV), sb + l * NSV, cur, oth, tid);
        p_matmul<32, true>(sm, pW + l * (NPV * NPV), pb + l * NPV, tid);
        float* t = cur; cur = oth; oth = t;
    }

    // ---- final projection ----
    means_s(sm, cur, NSV, tid);
    means_p(sm, NPV, tid);
    __syncthreads();
    fb_matmul<256, 32, false>(sm, vW, vb, cur, oth, tid);
    const float* sfin = oth;

    // ---- orbitals: sw[e][128] for both spins ----
    {
        int re = tid >> 5;                 // 0..7 (warp-uniform)
        int c0 = (tid & 31) << 2;          // 0..124
        float4 accu = *reinterpret_cast<const float4*>(wub + c0);
        float4 accd = *reinterpret_cast<const float4*>(wdb + c0);
        const float* su = sfin + re * NSV;
        const float* sd = sfin + (NU + re) * NSV;
        const float4* Wu = reinterpret_cast<const float4*>(wuW) + (c0 >> 2);
        const float4* Wd = reinterpret_cast<const float4*>(wdW) + (c0 >> 2);
#pragma unroll 4
        for (int k = 0; k < NSV; ++k) {
            float4 wu = __ldg(Wu + k * (NORB / 4));
            float4 wd = __ldg(Wd + k * (NORB / 4));
            float vu = su[k], vd = sd[k];
            accu.x = fmaf(vu, wu.x, accu.x); accu.y = fmaf(vu, wu.y, accu.y);
            accu.z = fmaf(vu, wu.z, accu.z); accu.w = fmaf(vu, wu.w, accu.w);
            accd.x = fmaf(vd, wd.x, accd.x); accd.y = fmaf(vd, wd.y, accd.y);
            accd.z = fmaf(vd, wd.z, accd.z); accd.w = fmaf(vd, wd.w, accd.w);
        }
        *reinterpret_cast<float4*>(sm->sw + re * NORB + c0) = accu;
        *reinterpret_cast<float4*>(sm->sw + (NU + re) * NORB + c0) = accd;
    }
    __syncthreads();

    // ---- 8x8 slogdets: one per thread (2 spins x 16 dets) ----
    if (tid < 32) {
        int spin = tid >> 4, d = tid & 15;
        const float* swp = sm->sw + spin * NU * NORB;
        const float* ev = sm->env + spin * NU;
        float M[8][8];
#pragma unroll
        for (int o = 0; o < 8; ++o)
#pragma unroll
            for (int e = 0; e < 8; ++e)
                M[o][e] = swp[e * NORB + o * NDET + d] * ev[e];
        float ld = 0.f, sg = 1.f;
        for (int k = 0; k < 8; ++k) {
            int piv = k;
            float mx = fabsf(M[k][k]);
            for (int i2 = k + 1; i2 < 8; ++i2) {
                float v = fabsf(M[i2][k]);
                if (v > mx) { mx = v; piv = i2; }
            }
            if (piv != k) {
                for (int j2 = 0; j2 < 8; ++j2) {
                    float t = M[k][j2]; M[k][j2] = M[piv][j2]; M[piv][j2] = t;
                }
                sg = -sg;
            }
            float pvv = M[k][k];
            ld += logf(fabsf(pvv));
            if (pvv < 0.f) sg = -sg;
            float inv = 1.0f / pvv;
            for (int i2 = k + 1; i2 < 8; ++i2) {
                float f = M[i2][k] * inv;
                for (int j2 = k + 1; j2 < 8; ++j2)
                    M[i2][j2] = fmaf(-f, M[k][j2], M[i2][j2]);
            }
        }
        sm->ldv[spin * NDET + d] = ld;
        sm->sgv[spin * NDET + d] = sg;
    }
    __syncthreads();

    // ---- combine ----
    if (tid == 0) {
        float ldt[NDET], sgt[NDET];
        float m = -3.402823e38f;
#pragma unroll
        for (int d = 0; d < NDET; ++d) {
            ldt[d] = sm->ldv[d] + sm->ldv[NDET + d];
            sgt[d] = sm->sgv[d] * sm->sgv[NDET + d];
            m = fmaxf(m, ldt[d]);
        }
        float s = 0.f;
#pragma unroll
        for (int d = 0; d < NDET; ++d)
            s += sgt[d] * expf(ldt[d] - m) * __ldg(wfW + d);
        out[b] = logf(fabsf(s)) + m;
    }
}

extern "C" void kernel_launch(void* const* d_in, const int* in_sizes, int n_in,
                              void* d_out, int out_size) {
    const float* r   = (const float*)d_in[0];
    const float* a   = (const float*)d_in[1];
    const float* sW0 = (const float*)d_in[2];
    const float* sb0 = (const float*)d_in[3];
    const float* sW  = (const float*)d_in[4];
    const float* sb  = (const float*)d_in[5];
    const float* pW0 = (const float*)d_in[6];
    const float* pb0 = (const float*)d_in[7];
    const float* pW  = (const float*)d_in[8];
    const float* pb  = (const float*)d_in[9];
    const float* vW  = (const float*)d_in[10];
    const float* vb  = (const float*)d_in[11];
    const float* wuW = (const float*)d_in[12];
    const float* wub = (const float*)d_in[13];
    const float* wdW = (const float*)d_in[14];
    const float* wdb = (const float*)d_in[15];
    const float* wfW = (const float*)d_in[16];
    float* out = (float*)d_out;

    int B = in_sizes[0] / (NE * 3);
    size_t smem = sizeof(SM);
    cudaFuncSetAttribute(ansatz_kernel, cudaFuncAttributeMaxDynamicSharedMemorySize,
                         (int)smem);
    ansatz_kernel<<<B, NTH, smem>>>(r, a, sW0, sb0, sW, sb, pW0, pb0, pW, pb,
                                    vW, vb, wuW, wub, wdW, wdb, wfW, out);
}

// round 4
// speedup vs baseline: 1.3957x; 1.3957x over previous
#include <cuda_runtime.h>
#include <math.h>

#define NE   16
#define NU   8
#define NA   4
#define NSV  256
#define NPV  32
#define PSTR 33
#define NFB  4
#define NDET 16
#define NORB 128
#define NTH  256

typedef unsigned long long u64;

#define FFMA2(d, a, b) asm volatile("fma.rn.f32x2 %0, %1, %2, %0;" : "+l"(d) : "l"(a), "l"(b))

__device__ __forceinline__ u64 pk2(float x, float y) {
    u64 d;
    asm("mov.b64 %0, {%1, %2};" : "=l"(d) : "r"(__float_as_uint(x)), "r"(__float_as_uint(y)));
    return d;
}
__device__ __forceinline__ float2 upk2(u64 d) {
    unsigned int lo, hi;
    asm("mov.b64 {%0, %1}, %2;" : "=r"(lo), "=r"(hi) : "l"(d));
    return make_float2(__uint_as_float(lo), __uint_as_float(hi));
}

struct SM {
    float s_a[NE * NSV];     // 4096
    float s_b[NE * NSV];     // 4096
    float p[NE * NE * PSTR]; // 8448 ; aliased post-stream: sw[2048] | opart[6144] | ldv/sgv
    float m2[2 * NSV];       // [mu ; md] contiguous
    float pu[NE * NPV];
    float pd[NE * NPV];
    float scratchB[4 * NSV]; // phase-1 per-k-group partials (g0 carries bias)
    float part[NE * NSV];    // phase-2 kg1 partials
    float pw[NPV * NPV];
    float pbv[NPV];
    float r_s[NE * 3];
    float a_s[NA * 3];
    float env[NE];
};

__device__ __forceinline__ int imin(int a, int b) { return a < b ? a : b; }
__device__ __forceinline__ int imax(int a, int b) { return a > b ? a : b; }

// 8 rows x 4 cols accumulate over a k-segment; weights via LDG.128, acts via LDS.128/4k.
__device__ __forceinline__ void acc_seg8(u64 acc[16], const float* __restrict__ Wp,
                                         const float* act, int astride, int n4) {
#pragma unroll 1
    for (int t = 0; t < n4; ++t) {
        float4 w0 = __ldg((const float4*)(Wp + 0 * NSV));
        float4 w1 = __ldg((const float4*)(Wp + 1 * NSV));
        float4 w2 = __ldg((const float4*)(Wp + 2 * NSV));
        float4 w3 = __ldg((const float4*)(Wp + 3 * NSV));
        u64 w0a = pk2(w0.x, w0.y), w0b = pk2(w0.z, w0.w);
        u64 w1a = pk2(w1.x, w1.y), w1b = pk2(w1.z, w1.w);
        u64 w2a = pk2(w2.x, w2.y), w2b = pk2(w2.z, w2.w);
        u64 w3a = pk2(w3.x, w3.y), w3b = pk2(w3.z, w3.w);
#pragma unroll
        for (int r = 0; r < 8; ++r) {
            float4 v = *(const float4*)(act + r * astride);
            u64 vv;
            vv = pk2(v.x, v.x); FFMA2(acc[2 * r], vv, w0a); FFMA2(acc[2 * r + 1], vv, w0b);
            vv = pk2(v.y, v.y); FFMA2(acc[2 * r], vv, w1a); FFMA2(acc[2 * r + 1], vv, w1b);
            vv = pk2(v.z, v.z); FFMA2(acc[2 * r], vv, w2a); FFMA2(acc[2 * r + 1], vv, w2b);
            vv = pk2(v.w, v.w); FFMA2(acc[2 * r], vv, w3a); FFMA2(acc[2 * r + 1], vv, w3b);
        }
        Wp += 4 * NSV;
        act += 4;
    }
}

// Phase 1: base[c] = bias[c] + [mu;md] @ W rows [KS,3KS). 4 k-groups x 64 col-threads.
template <int KS>
__device__ __forceinline__ void fb_base(SM* sm, const float* __restrict__ W,
                                        const float* __restrict__ bias, int tid) {
    const int g = tid >> 6, ct = tid & 63, c0 = ct * 4;
    const int C = (2 * KS) / 4;      // k-chunk per group
    const int k0 = g * C;
    float4 a4 = make_float4(0.f, 0.f, 0.f, 0.f);
    if (g == 0) a4 = *(const float4*)(bias + c0);
    const float* Wp = W + (KS + k0) * NSV + c0;
    const float* mp = sm->m2 + k0;
#pragma unroll 1
    for (int t = 0; t < C / 4; ++t) {
        float4 m  = *(const float4*)(mp);
        float4 w0 = __ldg((const float4*)(Wp + 0 * NSV));
        float4 w1 = __ldg((const float4*)(Wp + 1 * NSV));
        float4 w2 = __ldg((const float4*)(Wp + 2 * NSV));
        float4 w3 = __ldg((const float4*)(Wp + 3 * NSV));
        a4.x = fmaf(m.x, w0.x, fmaf(m.y, w1.x, fmaf(m.z, w2.x, fmaf(m.w, w3.x, a4.x))));
        a4.y = fmaf(m.x, w0.y, fmaf(m.y, w1.y, fmaf(m.z, w2.y, fmaf(m.w, w3.y, a4.y))));
        a4.z = fmaf(m.x, w0.z, fmaf(m.y, w1.z, fmaf(m.z, w2.z, fmaf(m.w, w3.z, a4.z))));
        a4.w = fmaf(m.x, w0.w, fmaf(m.y, w1.w, fmaf(m.z, w2.w, fmaf(m.w, w3.w, a4.w))));
        Wp += 4 * NSV;
        mp += 4;
    }
    *(float4*)(sm->scratchB + g * NSV + c0) = a4;
}

// Phase 2: per-row part. 2 row-groups x 64 col-threads x 2 k-halves; kg1 -> smem partial.
template <int KS, int KP, bool RES>
__device__ __forceinline__ void fb2(SM* sm, const float* __restrict__ W,
                                    const float* sin_, float* sout, int tid) {
    const int kg = tid >> 7;
    const int rg = (tid >> 6) & 1;
    const int c0 = (tid & 63) * 4;
    const int r0 = rg * 8;
    const int K = KS + 2 * KP;
    const int H = K / 2;
    u64 acc[16];
#pragma unroll
    for (int i = 0; i < 16; ++i) acc[i] = 0ull;
    const int ka = kg * H, kb = ka + H;
    {   // s-rows segment: unified k in [0,KS), W row = k
        int a = imax(ka, 0), b = imin(kb, KS);
        if (b > a) acc_seg8(acc, W + a * NSV + c0, sin_ + r0 * NSV + a, NSV, (b - a) / 4);
    }
    {   // pu segment: k in [KS,KS+KP), W row = 2*KS + k
        int a = imax(ka, KS), b = imin(kb, KS + KP);
        if (b > a) acc_seg8(acc, W + (2 * KS + a) * NSV + c0, sm->pu + r0 * NPV + (a - KS), NPV, (b - a) / 4);
    }
    {   // pd segment: k in [KS+KP,K), W row = 2*KS + k
        int a = imax(ka, KS + KP), b = imin(kb, K);
        if (b > a) acc_seg8(acc, W + (2 * KS + a) * NSV + c0, sm->pd + r0 * NPV + (a - KS - KP), NPV, (b - a) / 4);
    }
    if (kg == 1) {
#pragma unroll
        for (int r = 0; r < 8; ++r) {
            float2 a0 = upk2(acc[2 * r]), a1 = upk2(acc[2 * r + 1]);
            *(float4*)(sm->part + (r0 + r) * NSV + c0) = make_float4(a0.x, a0.y, a1.x, a1.y);
        }
    }
    __syncthreads();
    if (kg == 0) {
        float4 b0 = *(const float4*)(sm->scratchB + 0 * NSV + c0);
        float4 b1 = *(const float4*)(sm->scratchB + 1 * NSV + c0);
        float4 b2 = *(const float4*)(sm->scratchB + 2 * NSV + c0);
        float4 b3 = *(const float4*)(sm->scratchB + 3 * NSV + c0);
        float4 bb = make_float4(b0.x + b1.x + b2.x + b3.x, b0.y + b1.y + b2.y + b3.y,
                                b0.z + b1.z + b2.z + b3.z, b0.w + b1.w + b2.w + b3.w);
#pragma unroll
        for (int r = 0; r < 8; ++r) {
            float2 a0 = upk2(acc[2 * r]), a1 = upk2(acc[2 * r + 1]);
            float4 pp = *(const float4*)(sm->part + (r0 + r) * NSV + c0);
            float4 o;
            o.x = tanhf(a0.x + pp.x + bb.x);
            o.y = tanhf(a0.y + pp.y + bb.y);
            o.z = tanhf(a1.x + pp.z + bb.z);
            o.w = tanhf(a1.y + pp.w + bb.w);
            if (RES) {
                float4 rr = *(const float4*)(sin_ + (r0 + r) * NSV + c0);
                o.x += rr.x; o.y += rr.y; o.z += rr.z; o.w += rr.w;
            }
            *(float4*)(sout + (r0 + r) * NSV + c0) = o;
        }
    }
    __syncthreads();
}

template <int KIN, bool RES>
__device__ __forceinline__ void p_mm(SM* sm, const float* __restrict__ W,
                                     const float* __restrict__ bias, int tid) {
    for (int i = tid; i < KIN * NPV; i += NTH) sm->pw[i] = __ldg(W + i);
    if (tid < NPV) sm->pbv[tid] = __ldg(bias + tid);
    __syncthreads();
    float* prow = sm->p + tid * PSTR;
    float pin[KIN];
#pragma unroll
    for (int k = 0; k < KIN; ++k) pin[k] = prow[k];
    float outv[NPV];
#pragma unroll
    for (int cb = 0; cb < NPV; cb += 4) {
        float4 a = *(const float4*)(sm->pbv + cb);
#pragma unroll
        for (int k = 0; k < KIN; ++k) {
            float4 w = *(const float4*)(sm->pw + k * NPV + cb);
            a.x = fmaf(pin[k], w.x, a.x); a.y = fmaf(pin[k], w.y, a.y);
            a.z = fmaf(pin[k], w.z, a.z); a.w = fmaf(pin[k], w.w, a.w);
        }
        outv[cb + 0] = tanhf(a.x); outv[cb + 1] = tanhf(a.y);
        outv[cb + 2] = tanhf(a.z); outv[cb + 3] = tanhf(a.w);
    }
#pragma unroll
    for (int c = 0; c < NPV; ++c) prow[c] = RES ? (outv[c] + pin[c]) : outv[c];
    __syncthreads();
}

template <int KS>
__device__ __forceinline__ void means_s(SM* sm, const float* s, int tid) {
    if (tid < KS) {
        float a = 0.f, b = 0.f;
#pragma unroll
        for (int e = 0; e < NU; ++e) a += s[e * NSV + tid];
#pragma unroll
        for (int e = NU; e < NE; ++e) b += s[e * NSV + tid];
        sm->m2[tid] = a * 0.125f;
        sm->m2[KS + tid] = b * 0.125f;
    }
}

__device__ __forceinline__ void means_p(SM* sm, int kp, int tid) {
    for (int idx = tid; idx < NE * NPV; idx += NTH) {
        int j = idx >> 5, f = idx & 31;
        if (f < kp) {
            float a = 0.f, b = 0.f;
#pragma unroll
            for (int i = 0; i < NU; ++i) a += sm->p[(i * NE + j) * PSTR + f];
#pragma unroll
            for (int i = NU; i < NE; ++i) b += sm->p[(i * NE + j) * PSTR + f];
            sm->pu[j * NPV + f] = a * 0.125f;
            sm->pd[j * NPV + f] = b * 0.125f;
        }
    }
}

// Orbitals: 2 spins x 4 k-chunks, 32 col-threads, 8 rows x 4 cols per thread.
__device__ __forceinline__ void orbitals(SM* sm, const float* sfin,
                                         const float* __restrict__ wuW, const float* __restrict__ wub,
                                         const float* __restrict__ wdW, const float* __restrict__ wdb,
                                         int tid) {
    const int g = tid >> 5, c0 = (tid & 31) * 4;
    const int spin = g >> 2, kc = g & 3;
    const float* W = spin ? wdW : wuW;
    const float* bias = spin ? wdb : wub;
    const int e0 = spin * 8;
    float4 acc[8];
#pragma unroll
    for (int r = 0; r < 8; ++r) acc[r] = make_float4(0.f, 0.f, 0.f, 0.f);
    const float* Wp = W + (kc * 64) * NORB + c0;
    const float* ap = sfin + e0 * NSV + kc * 64;
#pragma unroll 1
    for (int t = 0; t < 16; ++t) {
        float4 w0 = __ldg((const float4*)(Wp + 0 * NORB));
        float4 w1 = __ldg((const float4*)(Wp + 1 * NORB));
        float4 w2 = __ldg((const float4*)(Wp + 2 * NORB));
        float4 w3 = __ldg((const float4*)(Wp + 3 * NORB));
#pragma unroll
        for (int r = 0; r < 8; ++r) {
            float4 v = *(const float4*)(ap + r * NSV);
            acc[r].x = fmaf(v.x, w0.x, fmaf(v.y, w1.x, fmaf(v.z, w2.x, fmaf(v.w, w3.x, acc[r].x))));
            acc[r].y = fmaf(v.x, w0.y, fmaf(v.y, w1.y, fmaf(v.z, w2.y, fmaf(v.w, w3.y, acc[r].y))));
            acc[r].z = fmaf(v.x, w0.z, fmaf(v.y, w1.z, fmaf(v.z, w2.z, fmaf(v.w, w3.z, acc[r].z))));
            acc[r].w = fmaf(v.x, w0.w, fmaf(v.y, w1.w, fmaf(v.z, w2.w, fmaf(v.w, w3.w, acc[r].w))));
        }
        Wp += 4 * NORB;
        ap += 4;
    }
    float* opart = sm->p + 2048;
    if (kc) {
#pragma unroll
        for (int r = 0; r < 8; ++r)
            *(float4*)(opart + (spin * 3 + kc - 1) * 1024 + r * NORB + c0) = acc[r];
    }
    __syncthreads();
    if (kc == 0) {
        float* sw = sm->p;
        float4 b4 = *(const float4*)(bias + c0);
#pragma unroll
        for (int r = 0; r < 8; ++r) {
            float4 s = acc[r];
            float4 p0 = *(const float4*)(opart + (spin * 3 + 0) * 1024 + r * NORB + c0);
            float4 p1 = *(const float4*)(opart + (spin * 3 + 1) * 1024 + r * NORB + c0);
            float4 p2 = *(const float4*)(opart + (spin * 3 + 2) * 1024 + r * NORB + c0);
            float ev = sm->env[e0 + r];
            float4 o;
            o.x = (s.x + p0.x + p1.x + p2.x + b4.x) * ev;
            o.y = (s.y + p0.y + p1.y + p2.y + b4.y) * ev;
            o.z = (s.z + p0.z + p1.z + p2.z + b4.z) * ev;
            o.w = (s.w + p0.w + p1.w + p2.w + b4.w) * ev;
            *(float4*)(sw + (e0 + r) * NORB + c0) = o;
        }
    }
    __syncthreads();
}

__global__ void __launch_bounds__(NTH, 2) ansatz_kernel(
    const float* __restrict__ r, const float* __restrict__ a,
    const float* __restrict__ sW0, const float* __restrict__ sb0,
    const float* __restrict__ sW, const float* __restrict__ sb,
    const float* __restrict__ pW0, const float* __restrict__ pb0,
    const float* __restrict__ pW, const float* __restrict__ pb,
    const float* __restrict__ vW, const float* __restrict__ vb,
    const float* __restrict__ wuW, const float* __restrict__ wub,
    const float* __restrict__ wdW, const float* __restrict__ wdb,
    const float* __restrict__ wfW, float* __restrict__ out) {
    extern __shared__ float smem_raw[];
    SM* sm = reinterpret_cast<SM*>(smem_raw);
    const int tid = threadIdx.x;
    const int b = blockIdx.x;

    if (tid < NE * 3) sm->r_s[tid] = r[b * NE * 3 + tid];
    if (tid >= 64 && tid < 64 + NA * 3) sm->a_s[tid - 64] = a[tid - 64];
    __syncthreads();

    // ---- embedding ----
    if (tid < NE) {
        int e = tid;
        float rx = sm->r_s[e * 3], ry = sm->r_s[e * 3 + 1], rz = sm->r_s[e * 3 + 2];
        float envv = 0.f;
#pragma unroll
        for (int at = 0; at < NA; ++at) {
            float dx = rx - sm->a_s[at * 3];
            float dy = ry - sm->a_s[at * 3 + 1];
            float dz = rz - sm->a_s[at * 3 + 2];
            float l = sqrtf(dx * dx + dy * dy + dz * dz);
            sm->s_a[e * NSV + at * 4 + 0] = dx;
            sm->s_a[e * NSV + at * 4 + 1] = dy;
            sm->s_a[e * NSV + at * 4 + 2] = dz;
            sm->s_a[e * NSV + at * 4 + 3] = l;
            envv += expf(-l);
        }
        sm->env[e] = envv;
    }
    {
        int i = tid >> 4, j = tid & 15;
        float dx = sm->r_s[j * 3 + 0] - sm->r_s[i * 3 + 0];
        float dy = sm->r_s[j * 3 + 1] - sm->r_s[i * 3 + 1];
        float dz = sm->r_s[j * 3 + 2] - sm->r_s[i * 3 + 2];
        float l = (i == j) ? sqrtf(3.0f) : sqrtf(dx * dx + dy * dy + dz * dz);
        float* prow = sm->p + tid * PSTR;
        prow[0] = dx; prow[1] = dy; prow[2] = dz; prow[3] = l;
    }
    __syncthreads();

    // ---- layer 0 ----
    means_s<16>(sm, sm->s_a, tid);
    means_p(sm, 4, tid);
    __syncthreads();
    fb_base<16>(sm, sW0, sb0, tid);
    __syncthreads();
    fb2<16, 4, false>(sm, sW0, sm->s_a, sm->s_b, tid);
    p_mm<4, false>(sm, pW0, pb0, tid);

    // ---- residual layers ----
    float* cur = sm->s_b;
    float* oth = sm->s_a;
    for (int l = 0; l < NFB; ++l) {
        means_s<256>(sm, cur, tid);
        means_p(sm, NPV, tid);
        __syncthreads();
        const float* Wl = sW + l * (832 * NSV);
        fb_base<256>(sm, Wl, sb + l * NSV, tid);
        __syncthreads();
        fb2<256, 32, true>(sm, Wl, cur, oth, tid);
        p_mm<32, true>(sm, pW + l * (NPV * NPV), pb + l * NPV, tid);
        float* t = cur; cur = oth; oth = t;
    }

    // ---- final projection ----
    means_s<256>(sm, cur, tid);
    means_p(sm, NPV, tid);
    __syncthreads();
    fb_base<256>(sm, vW, vb, tid);
    __syncthreads();
    fb2<256, 32, false>(sm, vW, cur, oth, tid);
    const float* sfin = oth;

    // ---- orbitals (writes sw into p-region alias) ----
    orbitals(sm, sfin, wuW, wub, wdW, wdb, tid);

    // ---- 8x8 slogdets ----
    float* ldv = sm->p + 8192;
    float* sgv = ldv + 2 * NDET;
    if (tid < 32) {
        int spin = tid >> 4, d = tid & 15;
        const float* swp = sm->p + spin * NU * NORB;
        float M[8][8];
#pragma unroll
        for (int o = 0; o < 8; ++o)
#pragma unroll
            for (int e = 0; e < 8; ++e)
                M[o][e] = swp[e * NORB + o * NDET + d];
        float ld = 0.f, sg = 1.f;
        for (int k = 0; k < 8; ++k) {
            int piv = k;
            float mx = fabsf(M[k][k]);
            for (int i2 = k + 1; i2 < 8; ++i2) {
                float v = fabsf(M[i2][k]);
                if (v > mx) { mx = v; piv = i2; }
            }
            if (piv != k) {
                for (int j2 = 0; j2 < 8; ++j2) {
                    float t = M[k][j2]; M[k][j2] = M[piv][j2]; M[piv][j2] = t;
                }
                sg = -sg;
            }
            float pvv = M[k][k];
            ld += logf(fabsf(pvv));
            if (pvv < 0.f) sg = -sg;
            float inv = 1.0f / pvv;
            for (int i2 = k + 1; i2 < 8; ++i2) {
                float f = M[i2][k] * inv;
                for (int j2 = k + 1; j2 < 8; ++j2)
                    M[i2][j2] = fmaf(-f, M[k][j2], M[i2][j2]);
            }
        }
        ldv[spin * NDET + d] = ld;
        sgv[spin * NDET + d] = sg;
    }
    __syncthreads();

    // ---- combine ----
    if (tid == 0) {
        float m = -3.402823e38f;
        float ldt[NDET], sgt[NDET];
#pragma unroll
        for (int d = 0; d < NDET; ++d) {
            ldt[d] = ldv[d] + ldv[NDET + d];
            sgt[d] = sgv[d] * sgv[NDET + d];
            m = fmaxf(m, ldt[d]);
        }
        float s = 0.f;
#pragma unroll
        for (int d = 0; d < NDET; ++d)
            s += sgt[d] * expf(ldt[d] - m) * __ldg(wfW + d);
        out[b] = logf(fabsf(s)) + m;
    }
}

extern "C" void kernel_launch(void* const* d_in, const int* in_sizes, int n_in,
                              void* d_out, int out_size) {
    const float* r   = (const float*)d_in[0];
    const float* a   = (const float*)d_in[1];
    const float* sW0 = (const float*)d_in[2];
    const float* sb0 = (const float*)d_in[3];
    const float* sW  = (const float*)d_in[4];
    const float* sb  = (const float*)d_in[5];
    const float* pW0 = (const float*)d_in[6];
    const float* pb0 = (const float*)d_in[7];
    const float* pW  = (const float*)d_in[8];
    const float* pb  = (const float*)d_in[9];
    const float* vW  = (const float*)d_in[10];
    const float* vb  = (const float*)d_in[11];
    const float* wuW = (const float*)d_in[12];
    const float* wub = (const float*)d_in[13];
    const float* wdW = (const float*)d_in[14];
    const float* wdb = (const float*)d_in[15];
    const float* wfW = (const float*)d_in[16];
    float* out = (float*)d_out;

    int B = in_sizes[0] / (NE * 3);
    size_t smem = sizeof(SM);
    cudaFuncSetAttribute(ansatz_kernel, cudaFuncAttributeMaxDynamicSharedMemorySize,
                         (int)smem);
    ansatz_kernel<<<B, NTH, smem>>>(r, a, sW0, sb0, sW, sb, pW0, pb0, pW, pb,
                                    vW, vb, wuW, wub, wdW, wdb, wfW, out);
}

// round 5
// speedup vs baseline: 1.4626x; 1.0479x over previous
#include <cuda_runtime.h>
#include <math.h>

#define NE   16
#define NU   8
#define NA   4
#define NSV  256
#define NPV  32
#define PSTR 33
#define NFB  4
#define NDET 16
#define NORB 128
#define NTH  256

typedef unsigned long long u64;

#define FFMA2(d, a, b) asm volatile("fma.rn.f32x2 %0, %1, %2, %0;" : "+l"(d) : "l"(a), "l"(b))

__device__ __forceinline__ u64 pk2(float x, float y) {
    u64 d;
    asm("mov.b64 %0, {%1, %2};" : "=l"(d) : "r"(__float_as_uint(x)), "r"(__float_as_uint(y)));
    return d;
}
__device__ __forceinline__ float2 upk2(u64 d) {
    unsigned int lo, hi;
    asm("mov.b64 {%0, %1}, %2;" : "=r"(lo), "=r"(hi) : "l"(d));
    return make_float2(__uint_as_float(lo), __uint_as_float(hi));
}

struct SM {
    float s_a[NE * NSV];     // 4096
    float s_b[NE * NSV];     // 4096
    float p[NE * NE * PSTR]; // 8448 ; aliased post-stream: sw[2048] | opart[6144] | ldv/sgv
    float m2[2 * NSV];       // [mu ; md] contiguous
    float pu[NE * NPV];
    float pd[NE * NPV];
    float scratchB[4 * NSV]; // phase-1 per-k-group partials (g0 carries bias)
    float part[NE * NSV];    // phase-2 kg1 partials
    float pw[NPV * NPV];
    float pbv[NPV];
    float r_s[NE * 3];
    float a_s[NA * 3];
    float env[NE];
};

__device__ __forceinline__ int imin(int a, int b) { return a < b ? a : b; }
__device__ __forceinline__ int imax(int a, int b) { return a > b ? a : b; }

// 8 rows x 4 cols accumulate over a k-segment; weights via LDG.128, acts via LDS.128/4k.
__device__ __forceinline__ void acc_seg8(u64 acc[16], const float* __restrict__ Wp,
                                         const float* act, int astride, int n4) {
#pragma unroll 1
    for (int t = 0; t < n4; ++t) {
        float4 w0 = __ldg((const float4*)(Wp + 0 * NSV));
        float4 w1 = __ldg((const float4*)(Wp + 1 * NSV));
        float4 w2 = __ldg((const float4*)(Wp + 2 * NSV));
        float4 w3 = __ldg((const float4*)(Wp + 3 * NSV));
        u64 w0a = pk2(w0.x, w0.y), w0b = pk2(w0.z, w0.w);
        u64 w1a = pk2(w1.x, w1.y), w1b = pk2(w1.z, w1.w);
        u64 w2a = pk2(w2.x, w2.y), w2b = pk2(w2.z, w2.w);
        u64 w3a = pk2(w3.x, w3.y), w3b = pk2(w3.z, w3.w);
#pragma unroll
        for (int r = 0; r < 8; ++r) {
            float4 v = *(const float4*)(act + r * astride);
            u64 vv;
            vv = pk2(v.x, v.x); FFMA2(acc[2 * r], vv, w0a); FFMA2(acc[2 * r + 1], vv, w0b);
            vv = pk2(v.y, v.y); FFMA2(acc[2 * r], vv, w1a); FFMA2(acc[2 * r + 1], vv, w1b);
            vv = pk2(v.z, v.z); FFMA2(acc[2 * r], vv, w2a); FFMA2(acc[2 * r + 1], vv, w2b);
            vv = pk2(v.w, v.w); FFMA2(acc[2 * r], vv, w3a); FFMA2(acc[2 * r + 1], vv, w3b);
        }
        Wp += 4 * NSV;
        act += 4;
    }
}

// Phase 1: base[c] = bias[c] + [mu;md] @ W rows [KS,3KS). 4 k-groups x 64 col-threads.
template <int KS>
__device__ __forceinline__ void fb_base(SM* sm, const float* __restrict__ W,
                                        const float* __restrict__ bias, int tid) {
    const int g = tid >> 6, ct = tid & 63, c0 = ct * 4;
    const int C = (2 * KS) / 4;      // k-chunk per group
    const int k0 = g * C;
    float4 a4 = make_float4(0.f, 0.f, 0.f, 0.f);
    if (g == 0) a4 = *(const float4*)(bias + c0);
    const float* Wp = W + (KS + k0) * NSV + c0;
    const float* mp = sm->m2 + k0;
#pragma unroll 1
    for (int t = 0; t < C / 4; ++t) {
        float4 m  = *(const float4*)(mp);
        float4 w0 = __ldg((const float4*)(Wp + 0 * NSV));
        float4 w1 = __ldg((const float4*)(Wp + 1 * NSV));
        float4 w2 = __ldg((const float4*)(Wp + 2 * NSV));
        float4 w3 = __ldg((const float4*)(Wp + 3 * NSV));
        a4.x = fmaf(m.x, w0.x, fmaf(m.y, w1.x, fmaf(m.z, w2.x, fmaf(m.w, w3.x, a4.x))));
        a4.y = fmaf(m.x, w0.y, fmaf(m.y, w1.y, fmaf(m.z, w2.y, fmaf(m.w, w3.y, a4.y))));
        a4.z = fmaf(m.x, w0.z, fmaf(m.y, w1.z, fmaf(m.z, w2.z, fmaf(m.w, w3.z, a4.z))));
        a4.w = fmaf(m.x, w0.w, fmaf(m.y, w1.w, fmaf(m.z, w2.w, fmaf(m.w, w3.w, a4.w))));
        Wp += 4 * NSV;
        mp += 4;
    }
    *(float4*)(sm->scratchB + g * NSV + c0) = a4;
}

// Phase 2: per-row part. 2 row-groups x 64 col-threads x 2 k-halves; kg1 -> smem partial.
template <int KS, int KP, bool RES>
__device__ __forceinline__ void fb2(SM* sm, const float* __restrict__ W,
                                    const float* sin_, float* sout, int tid) {
    const int kg = tid >> 7;
    const int rg = (tid >> 6) & 1;
    const int c0 = (tid & 63) * 4;
    const int r0 = rg * 8;
    const int K = KS + 2 * KP;
    const int H = K / 2;
    u64 acc[16];
#pragma unroll
    for (int i = 0; i < 16; ++i) acc[i] = 0ull;
    const int ka = kg * H, kb = ka + H;
    {   // s-rows segment: unified k in [0,KS), W row = k
        int a = imax(ka, 0), b = imin(kb, KS);
        if (b > a) acc_seg8(acc, W + a * NSV + c0, sin_ + r0 * NSV + a, NSV, (b - a) / 4);
    }
    {   // pu segment: k in [KS,KS+KP), W row = 2*KS + k
        int a = imax(ka, KS), b = imin(kb, KS + KP);
        if (b > a) acc_seg8(acc, W + (2 * KS + a) * NSV + c0, sm->pu + r0 * NPV + (a - KS), NPV, (b - a) / 4);
    }
    {   // pd segment: k in [KS+KP,K), W row = 2*KS + k
        int a = imax(ka, KS + KP), b = imin(kb, K);
        if (b > a) acc_seg8(acc, W + (2 * KS + a) * NSV + c0, sm->pd + r0 * NPV + (a - KS - KP), NPV, (b - a) / 4);
    }
    if (kg == 1) {
#pragma unroll
        for (int r = 0; r < 8; ++r) {
            float2 a0 = upk2(acc[2 * r]), a1 = upk2(acc[2 * r + 1]);
            *(float4*)(sm->part + (r0 + r) * NSV + c0) = make_float4(a0.x, a0.y, a1.x, a1.y);
        }
    }
    __syncthreads();
    if (kg == 0) {
        float4 b0 = *(const float4*)(sm->scratchB + 0 * NSV + c0);
        float4 b1 = *(const float4*)(sm->scratchB + 1 * NSV + c0);
        float4 b2 = *(const float4*)(sm->scratchB + 2 * NSV + c0);
        float4 b3 = *(const float4*)(sm->scratchB + 3 * NSV + c0);
        float4 bb = make_float4(b0.x + b1.x + b2.x + b3.x, b0.y + b1.y + b2.y + b3.y,
                                b0.z + b1.z + b2.z + b3.z, b0.w + b1.w + b2.w + b3.w);
#pragma unroll
        for (int r = 0; r < 8; ++r) {
            float2 a0 = upk2(acc[2 * r]), a1 = upk2(acc[2 * r + 1]);
            float4 pp = *(const float4*)(sm->part + (r0 + r) * NSV + c0);
            float4 o;
            o.x = tanhf(a0.x + pp.x + bb.x);
            o.y = tanhf(a0.y + pp.y + bb.y);
            o.z = tanhf(a1.x + pp.z + bb.z);
            o.w = tanhf(a1.y + pp.w + bb.w);
            if (RES) {
                float4 rr = *(const float4*)(sin_ + (r0 + r) * NSV + c0);
                o.x += rr.x; o.y += rr.y; o.z += rr.z; o.w += rr.w;
            }
            *(float4*)(sout + (r0 + r) * NSV + c0) = o;
        }
    }
    __syncthreads();
}

template <int KIN, bool RES>
__device__ __forceinline__ void p_mm(SM* sm, const float* __restrict__ W,
                                     const float* __restrict__ bias, int tid) {
    for (int i = tid; i < KIN * NPV; i += NTH) sm->pw[i] = __ldg(W + i);
    if (tid < NPV) sm->pbv[tid] = __ldg(bias + tid);
    __syncthreads();
    float* prow = sm->p + tid * PSTR;
    float pin[KIN];
#pragma unroll
    for (int k = 0; k < KIN; ++k) pin[k] = prow[k];
    float outv[NPV];
#pragma unroll
    for (int cb = 0; cb < NPV; cb += 4) {
        float4 a = *(const float4*)(sm->pbv + cb);
#pragma unroll
        for (int k = 0; k < KIN; ++k) {
            float4 w = *(const float4*)(sm->pw + k * NPV + cb);
            a.x = fmaf(pin[k], w.x, a.x); a.y = fmaf(pin[k], w.y, a.y);
            a.z = fmaf(pin[k], w.z, a.z); a.w = fmaf(pin[k], w.w, a.w);
        }
        outv[cb + 0] = tanhf(a.x); outv[cb + 1] = tanhf(a.y);
        outv[cb + 2] = tanhf(a.z); outv[cb + 3] = tanhf(a.w);
    }
#pragma unroll
    for (int c = 0; c < NPV; ++c) prow[c] = RES ? (outv[c] + pin[c]) : outv[c];
    __syncthreads();
}

template <int KS>
__device__ __forceinline__ void means_s(SM* sm, const float* s, int tid) {
    if (tid < KS) {
        float a = 0.f, b = 0.f;
#pragma unroll
        for (int e = 0; e < NU; ++e) a += s[e * NSV + tid];
#pragma unroll
        for (int e = NU; e < NE; ++e) b += s[e * NSV + tid];
        sm->m2[tid] = a * 0.125f;
        sm->m2[KS + tid] = b * 0.125f;
    }
}

__device__ __forceinline__ void means_p(SM* sm, int kp, int tid) {
    for (int idx = tid; idx < NE * NPV; idx += NTH) {
        int j = idx >> 5, f = idx & 31;
        if (f < kp) {
            float a = 0.f, b = 0.f;
#pragma unroll
            for (int i = 0; i < NU; ++i) a += sm->p[(i * NE + j) * PSTR + f];
#pragma unroll
            for (int i = NU; i < NE; ++i) b += sm->p[(i * NE + j) * PSTR + f];
            sm->pu[j * NPV + f] = a * 0.125f;
            sm->pd[j * NPV + f] = b * 0.125f;
        }
    }
}

// Orbitals: 2 spins x 4 k-chunks, 32 col-threads, 8 rows x 4 cols per thread.
__device__ __forceinline__ void orbitals(SM* sm, const float* sfin,
                                         const float* __restrict__ wuW, const float* __restrict__ wub,
                                         const float* __restrict__ wdW, const float* __restrict__ wdb,
                                         int tid) {
    const int g = tid >> 5, c0 = (tid & 31) * 4;
    const int spin = g >> 2, kc = g & 3;
    const float* W = spin ? wdW : wuW;
    const float* bias = spin ? wdb : wub;
    const int e0 = spin * 8;
    float4 acc[8];
#pragma unroll
    for (int r = 0; r < 8; ++r) acc[r] = make_float4(0.f, 0.f, 0.f, 0.f);
    const float* Wp = W + (kc * 64) * NORB + c0;
    const float* ap = sfin + e0 * NSV + kc * 64;
#pragma unroll 1
    for (int t = 0; t < 16; ++t) {
        float4 w0 = __ldg((const float4*)(Wp + 0 * NORB));
        float4 w1 = __ldg((const float4*)(Wp + 1 * NORB));
        float4 w2 = __ldg((const float4*)(Wp + 2 * NORB));
        float4 w3 = __ldg((const float4*)(Wp + 3 * NORB));
#pragma unroll
        for (int r = 0; r < 8; ++r) {
            float4 v = *(const float4*)(ap + r * NSV);
            acc[r].x = fmaf(v.x, w0.x, fmaf(v.y, w1.x, fmaf(v.z, w2.x, fmaf(v.w, w3.x, acc[r].x))));
            acc[r].y = fmaf(v.x, w0.y, fmaf(v.y, w1.y, fmaf(v.z, w2.y, fmaf(v.w, w3.y, acc[r].y))));
            acc[r].z = fmaf(v.x, w0.z, fmaf(v.y, w1.z, fmaf(v.z, w2.z, fmaf(v.w, w3.z, acc[r].z))));
            acc[r].w = fmaf(v.x, w0.w, fmaf(v.y, w1.w, fmaf(v.z, w2.w, fmaf(v.w, w3.w, acc[r].w))));
        }
        Wp += 4 * NORB;
        ap += 4;
    }
    float* opart = sm->p + 2048;
    if (kc) {
#pragma unroll
        for (int r = 0; r < 8; ++r)
            *(float4*)(opart + (spin * 3 + kc - 1) * 1024 + r * NORB + c0) = acc[r];
    }
    __syncthreads();
    if (kc == 0) {
        float* sw = sm->p;
        float4 b4 = *(const float4*)(bias + c0);
#pragma unroll
        for (int r = 0; r < 8; ++r) {
            float4 s = acc[r];
            float4 p0 = *(const float4*)(opart + (spin * 3 + 0) * 1024 + r * NORB + c0);
            float4 p1 = *(const float4*)(opart + (spin * 3 + 1) * 1024 + r * NORB + c0);
            float4 p2 = *(const float4*)(opart + (spin * 3 + 2) * 1024 + r * NORB + c0);
            float ev = sm->env[e0 + r];
            float4 o;
            o.x = (s.x + p0.x + p1.x + p2.x + b4.x) * ev;
            o.y = (s.y + p0.y + p1.y + p2.y + b4.y) * ev;
            o.z = (s.z + p0.z + p1.z + p2.z + b4.z) * ev;
            o.w = (s.w + p0.w + p1.w + p2.w + b4.w) * ev;
            *(float4*)(sw + (e0 + r) * NORB + c0) = o;
        }
    }
    __syncthreads();
}

__global__ void __launch_bounds__(NTH, 2) ansatz_kernel(
    const float* __restrict__ r, const float* __restrict__ a,
    const float* __restrict__ sW0, const float* __restrict__ sb0,
    const float* __restrict__ sW, const float* __restrict__ sb,
    const float* __restrict__ pW0, const float* __restrict__ pb0,
    const float* __restrict__ pW, const float* __restrict__ pb,
    const float* __restrict__ vW, const float* __restrict__ vb,
    const float* __restrict__ wuW, const float* __restrict__ wub,
    const float* __restrict__ wdW, const float* __restrict__ wdb,
    const float* __restrict__ wfW, float* __restrict__ out) {
    extern __shared__ float smem_raw[];
    SM* sm = reinterpret_cast<SM*>(smem_raw);
    const int tid = threadIdx.x;
    const int b = blockIdx.x;

    if (tid < NE * 3) sm->r_s[tid] = r[b * NE * 3 + tid];
    if (tid >= 64 && tid < 64 + NA * 3) sm->a_s[tid - 64] = a[tid - 64];
    __syncthreads();

    // ---- embedding ----
    if (tid < NE) {
        int e = tid;
        float rx = sm->r_s[e * 3], ry = sm->r_s[e * 3 + 1], rz = sm->r_s[e * 3 + 2];
        float envv = 0.f;
#pragma unroll
        for (int at = 0; at < NA; ++at) {
            float dx = rx - sm->a_s[at * 3];
            float dy = ry - sm->a_s[at * 3 + 1];
            float dz = rz - sm->a_s[at * 3 + 2];
            float l = sqrtf(dx * dx + dy * dy + dz * dz);
            sm->s_a[e * NSV + at * 4 + 0] = dx;
            sm->s_a[e * NSV + at * 4 + 1] = dy;
            sm->s_a[e * NSV + at * 4 + 2] = dz;
            sm->s_a[e * NSV + at * 4 + 3] = l;
            envv += expf(-l);
        }
        sm->env[e] = envv;
    }
    {
        int i = tid >> 4, j = tid & 15;
        float dx = sm->r_s[j * 3 + 0] - sm->r_s[i * 3 + 0];
        float dy = sm->r_s[j * 3 + 1] - sm->r_s[i * 3 + 1];
        float dz = sm->r_s[j * 3 + 2] - sm->r_s[i * 3 + 2];
        float l = (i == j) ? sqrtf(3.0f) : sqrtf(dx * dx + dy * dy + dz * dz);
        float* prow = sm->p + tid * PSTR;
        prow[0] = dx; prow[1] = dy; prow[2] = dz; prow[3] = l;
    }
    __syncthreads();

    // ---- layer 0 ----
    means_s<16>(sm, sm->s_a, tid);
    means_p(sm, 4, tid);
    __syncthreads();
    fb_base<16>(sm, sW0, sb0, tid);
    __syncthreads();
    fb2<16, 4, false>(sm, sW0, sm->s_a, sm->s_b, tid);
    p_mm<4, false>(sm, pW0, pb0, tid);

    // ---- residual layers ----
    float* cur = sm->s_b;
    float* oth = sm->s_a;
    for (int l = 0; l < NFB; ++l) {
        means_s<256>(sm, cur, tid);
        means_p(sm, NPV, tid);
        __syncthreads();
        const float* Wl = sW + l * (832 * NSV);
        fb_base<256>(sm, Wl, sb + l * NSV, tid);
        __syncthreads();
        fb2<256, 32, true>(sm, Wl, cur, oth, tid);
        p_mm<32, true>(sm, pW + l * (NPV * NPV), pb + l * NPV, tid);
        float* t = cur; cur = oth; oth = t;
    }

    // ---- final projection ----
    means_s<256>(sm, cur, tid);
    means_p(sm, NPV, tid);
    __syncthreads();
    fb_base<256>(sm, vW, vb, tid);
    __syncthreads();
    fb2<256, 32, false>(sm, vW, cur, oth, tid);
    const float* sfin = oth;

    // ---- orbitals (writes sw into p-region alias) ----
    orbitals(sm, sfin, wuW, wub, wdW, wdb, tid);

    // ---- 8x8 slogdets ----
    float* ldv = sm->p + 8192;
    float* sgv = ldv + 2 * NDET;
    if (tid < 32) {
        int spin = tid >> 4, d = tid & 15;
        const float* swp = sm->p + spin * NU * NORB;
        float M[8][8];
#pragma unroll
        for (int o = 0; o < 8; ++o)
#pragma unroll
            for (int e = 0; e < 8; ++e)
                M[o][e] = swp[e * NORB + o * NDET + d];
        float ld = 0.f, sg = 1.f;
        for (int k = 0; k < 8; ++k) {
            int piv = k;
            float mx = fabsf(M[k][k]);
            for (int i2 = k + 1; i2 < 8; ++i2) {
                float v = fabsf(M[i2][k]);
                if (v > mx) { mx = v; piv = i2; }
            }
            if (piv != k) {
                for (int j2 = 0; j2 < 8; ++j2) {
                    float t = M[k][j2]; M[k][j2] = M[piv][j2]; M[piv][j2] = t;
                }
                sg = -sg;
            }
            float pvv = M[k][k];
            ld += logf(fabsf(pvv));
            if (pvv < 0.f) sg = -sg;
            float inv = 1.0f / pvv;
            for (int i2 = k + 1; i2 < 8; ++i2) {
                float f = M[i2][k] * inv;
                for (int j2 = k + 1; j2 < 8; ++j2)
                    M[i2][j2] = fmaf(-f, M[k][j2], M[i2][j2]);
            }
        }
        ldv[spin * NDET + d] = ld;
        sgv[spin * NDET + d] = sg;
    }
    __syncthreads();

    // ---- combine ----
    if (tid == 0) {
        float m = -3.402823e38f;
        float ldt[NDET], sgt[NDET];
#pragma unroll
        for (int d = 0; d < NDET; ++d) {
            ldt[d] = ldv[d] + ldv[NDET + d];
            sgt[d] = sgv[d] * sgv[NDET + d];
            m = fmaxf(m, ldt[d]);
        }
        float s = 0.f;
#pragma unroll
        for (int d = 0; d < NDET; ++d)
            s += sgt[d] * expf(ldt[d] - m) * __ldg(wfW + d);
        out[b] = logf(fabsf(s)) + m;
    }
}

extern "C" void kernel_launch(void* const* d_in, const int* in_sizes, int n_in,
                              void* d_out, int out_size) {
    const float* r   = (const float*)d_in[0];
    const float* a   = (const float*)d_in[1];
    const float* sW0 = (const float*)d_in[2];
    const float* sb0 = (const float*)d_in[3];
    const float* sW  = (const float*)d_in[4];
    const float* sb  = (const float*)d_in[5];
    const float* pW0 = (const float*)d_in[6];
    const float* pb0 = (const float*)d_in[7];
    const float* pW  = (const float*)d_in[8];
    const float* pb  = (const float*)d_in[9];
    const float* vW  = (const float*)d_in[10];
    const float* vb  = (const float*)d_in[11];
    const float* wuW = (const float*)d_in[12];
    const float* wub = (const float*)d_in[13];
    const float* wdW = (const float*)d_in[14];
    const float* wdb = (const float*)d_in[15];
    const float* wfW = (const float*)d_in[16];
    float* out = (float*)d_out;

    int B = in_sizes[0] / (NE * 3);
    size_t smem = sizeof(SM);
    cudaFuncSetAttribute(ansatz_kernel, cudaFuncAttributeMaxDynamicSharedMemorySize,
                         (int)smem);
    ansatz_kernel<<<B, NTH, smem>>>(r, a, sW0, sb0, sW, sb, pW0, pb0, pW, pb,
                                    vW, vb, wuW, wub, wdW, wdb, wfW, out);
}